// round 4
// baseline (speedup 1.0000x reference)
#include <cuda_runtime.h>

#define LN 8      // layers
#define BN 64     // batch
#define TN 512    // time steps
#define HN 128    // hidden
#define ON 65     // output vocab
#define CPL 16    // CTAs per layer
#define UPC 8     // hidden units per CTA
#define GCOLS 32  // gate columns per CTA
#define NTHR 128
#define NCTA (LN * CPL)

typedef unsigned long long u64;

// Inter-layer activation buffer, k-major: h of layer l at time t, [HN][BN].
__device__ float g_hbuf[LN][TN][HN][BN];
// Per-slice completion flags: g_flag[l][t][slice] != 0 when that CTA published h(l,t).
__device__ int g_flag[LN][TN][CPL];

__device__ __forceinline__ float sig_(float x) {
    return __fdividef(1.f, 1.f + __expf(-x));
}
__device__ __forceinline__ float th_(float x) {
    return 1.f - __fdividef(2.f, __expf(2.f * x) + 1.f);
}

__device__ __forceinline__ int ld_acq(const int* p) {
    int v; asm volatile("ld.global.acquire.gpu.b32 %0, [%1];" : "=r"(v) : "l"(p)); return v;
}
__device__ __forceinline__ void st_rel(int* p, int v) {
    asm volatile("st.global.release.gpu.b32 [%0], %1;" :: "l"(p), "r"(v));
}
__device__ __forceinline__ u64 pk2(float x) {
    u64 d; asm("mov.b64 %0, {%1, %1};" : "=l"(d) : "f"(x)); return d;
}
__device__ __forceinline__ u64 pk(float lo, float hi) {
    u64 d; asm("mov.b64 %0, {%1, %2};" : "=l"(d) : "f"(lo), "f"(hi)); return d;
}
__device__ __forceinline__ void fma2(u64& d, u64 a, u64 b) {
    asm("fma.rn.f32x2 %0, %1, %2, %0;" : "+l"(d) : "l"(a), "l"(b));
}
__device__ __forceinline__ void upk(float& lo, float& hi, u64 v) {
    asm("mov.b64 {%0, %1}, %2;" : "=f"(lo), "=f"(hi) : "l"(v));
}

__global__ void __launch_bounds__(256, 1) zero_flag_kernel() {
    int i = blockIdx.x * blockDim.x + threadIdx.x;
    if (i < LN * TN * CPL) (&g_flag[0][0][0])[i] = 0;
}

__global__ void __launch_bounds__(NTHR, 1) lstm_kernel(
    const int* __restrict__ x, const float* __restrict__ embed,
    const float* __restrict__ w_ih, const float* __restrict__ b_ih,
    const float* __restrict__ w_hh, const float* __restrict__ b_hh,
    float* __restrict__ out, int out_size)
{
    extern __shared__ float sm[];
    float* w_s  = sm;          // [2][128][32]: w_ih then w_hh slice, layout [k][lu*4+g]
    float* in_s = sm + 8192;   // [128][64] k-major input tile
    float* hp_s = sm + 16384;  // [128][64] k-major h_prev tile

    const int cta   = blockIdx.x;
    const int l     = cta >> 4;
    const int slice = cta & 15;
    const int tid   = threadIdx.x;
    const int warp  = tid >> 5;    // cols warp*8 .. warp*8+7 (units warp*2, warp*2+1)
    const int lane  = tid & 31;    // rows lane, lane+32

    // ---- one-time: weight slice into SMEM ----
    for (int i = tid; i < HN * GCOLS; i += NTHR) {
        int k = i >> 5;
        int c = i & 31;            // c = lu*4 + g
        int lu = c >> 2, g = c & 3;
        int gc = g * HN + slice * UPC + lu;
        w_s[i]        = w_ih[(l * HN + k) * (4 * HN) + gc];
        w_s[4096 + i] = w_hh[(l * HN + k) * (4 * HN) + gc];
    }
    // bias pairs packed as f32x2: c2 index over (uu*2 + gpair)
    u64 bias2[4];
#pragma unroll
    for (int c2 = 0; c2 < 4; c2++) {
        int c0 = c2 * 2, c1 = c2 * 2 + 1;
        int uu0 = c0 >> 2, g0 = c0 & 3;
        int uu1 = c1 >> 2, g1 = c1 & 3;
        int gua = slice * UPC + warp * 2 + uu0;
        int gub = slice * UPC + warp * 2 + uu1;
        float ba = b_ih[l * 4 * HN + g0 * HN + gua] + b_hh[l * 4 * HN + g0 * HN + gua];
        float bb = b_ih[l * 4 * HN + g1 * HN + gub] + b_hh[l * 4 * HN + g1 * HN + gub];
        bias2[c2] = pk(ba, bb);
    }
    float cst[2][2] = {{0.f, 0.f}, {0.f, 0.f}};
    __syncthreads();

    for (int t = 0; t < TN; t++) {
        // ---- wait for both dependencies with one combined poll ----
        if (l > 0 || t > 0) {
            const int* fA = (l > 0) ? &g_flag[l - 1][t][0] : &g_flag[l][t - 1][0];
            const int* fB = (t > 0) ? &g_flag[l][t - 1][0] : fA;
            const int* mine = (lane < 16) ? (fA + lane) : (fB + (lane - 16));
            while (!__all_sync(0xffffffffu, ld_acq(mine) != 0)) { }
        }

        // ---- stage tiles ----
        if (l > 0 && t > 0) {
            const float4* s1 = (const float4*)&g_hbuf[l - 1][t][0][0];
            const float4* s2 = (const float4*)&g_hbuf[l][t - 1][0][0];
            for (int i = tid; i < 2048; i += NTHR) {
                float4 v1 = __ldcg(s1 + i);
                float4 v2 = __ldcg(s2 + i);
                ((float4*)in_s)[i] = v1;
                ((float4*)hp_s)[i] = v2;
            }
        } else {
            if (l == 0) {
                // embedding gather, k-major write (lanes -> consecutive rows)
                int r  = tid & 63;
                int kh = (tid >> 6) << 6;
                int tok = x[r * TN + t];
                const float* er = embed + tok * HN;
#pragma unroll
                for (int k = kh; k < kh + 64; k += 4) {
                    float4 v = *(const float4*)(er + k);
                    in_s[(k + 0) * BN + r] = v.x;
                    in_s[(k + 1) * BN + r] = v.y;
                    in_s[(k + 2) * BN + r] = v.z;
                    in_s[(k + 3) * BN + r] = v.w;
                }
            } else {
                const float4* s1 = (const float4*)&g_hbuf[l - 1][t][0][0];
                for (int i = tid; i < 2048; i += NTHR)
                    ((float4*)in_s)[i] = __ldcg(s1 + i);
            }
            if (t == 0) {
                for (int i = tid; i < 8192; i += NTHR) hp_s[i] = 0.f;
            } else {
                const float4* s2 = (const float4*)&g_hbuf[l][t - 1][0][0];
                for (int i = tid; i < 2048; i += NTHR)
                    ((float4*)hp_s)[i] = __ldcg(s2 + i);
            }
        }
        __syncthreads();

        // ---- gates via packed f32x2 FMA: acc2[row][colpair] ----
        u64 acc[2][4];
#pragma unroll
        for (int c2 = 0; c2 < 4; c2++) { acc[0][c2] = bias2[c2]; acc[1][c2] = bias2[c2]; }

        const u64* wi = (const u64*)(w_s + warp * 8);
        const u64* wh = (const u64*)(w_s + 4096 + warp * 8);
#pragma unroll 8
        for (int k = 0; k < HN; k++) {
            float a0 = in_s[k * BN + lane];
            float a1 = in_s[k * BN + lane + 32];
            float p0 = hp_s[k * BN + lane];
            float p1 = hp_s[k * BN + lane + 32];
            u64 A0 = pk2(a0), A1 = pk2(a1), P0 = pk2(p0), P1 = pk2(p1);
            const u64* wik = wi + k * (GCOLS / 2);
            const u64* whk = wh + k * (GCOLS / 2);
            u64 wv0 = wik[0], wv1 = wik[1], wv2 = wik[2], wv3 = wik[3];
            u64 hv0 = whk[0], hv1 = whk[1], hv2 = whk[2], hv3 = whk[3];
            fma2(acc[0][0], A0, wv0); fma2(acc[1][0], A1, wv0);
            fma2(acc[0][1], A0, wv1); fma2(acc[1][1], A1, wv1);
            fma2(acc[0][2], A0, wv2); fma2(acc[1][2], A1, wv2);
            fma2(acc[0][3], A0, wv3); fma2(acc[1][3], A1, wv3);
            fma2(acc[0][0], P0, hv0); fma2(acc[1][0], P1, hv0);
            fma2(acc[0][1], P0, hv1); fma2(acc[1][1], P1, hv1);
            fma2(acc[0][2], P0, hv2); fma2(acc[1][2], P1, hv2);
            fma2(acc[0][3], P0, hv3); fma2(acc[1][3], P1, hv3);
        }

        // ---- LSTM cell elementwise; publish h ----
#pragma unroll
        for (int rr = 0; rr < 2; rr++) {
            int r = lane + rr * 32;
#pragma unroll
            for (int uu = 0; uu < 2; uu++) {
                float gi, gf, gg, go;
                upk(gi, gf, acc[rr][uu * 2 + 0]);
                upk(gg, go, acc[rr][uu * 2 + 1]);
                float iv = sig_(gi);
                float fv = sig_(gf);
                float gv = th_(gg);
                float ov = sig_(go);
                float c  = fv * cst[rr][uu] + iv * gv;
                cst[rr][uu] = c;
                float h = ov * th_(c);
                int gu = slice * UPC + warp * 2 + uu;
                g_hbuf[l][t][gu][r] = h;
                if (t == TN - 1) {
                    int hidx = BN * TN * ON + (l * BN + r) * HN + gu;
                    int cidx = hidx + LN * BN * HN;
                    if (hidx < out_size) out[hidx] = h;
                    if (cidx < out_size) out[cidx] = c;
                }
            }
        }
        __threadfence();
        __syncthreads();
        if (tid == 0) st_rel(&g_flag[l][t][slice], 1);
    }
}

// outputs[b][t][o] = h7[t][b] . w_out[:,o] + b_out[o]; one CTA per t.
__global__ void __launch_bounds__(256, 1) proj_kernel(
    const float* __restrict__ w_out, const float* __restrict__ b_out,
    float* __restrict__ out, int out_size)
{
    extern __shared__ float sm[];
    float* h_s  = sm;          // [128][64]
    float* w_sm = sm + 8192;   // [128][65]
    int t = blockIdx.x;
    int tid = threadIdx.x;
    const float4* src = (const float4*)&g_hbuf[LN - 1][t][0][0];
    for (int i = tid; i < 2048; i += 256) ((float4*)h_s)[i] = src[i];
    for (int i = tid; i < HN * ON; i += 256) w_sm[i] = w_out[i];
    __syncthreads();
    for (int idx = tid; idx < BN * ON; idx += 256) {
        int b = idx / ON, o = idx - b * ON;
        float s = b_out[o];
#pragma unroll 16
        for (int k = 0; k < HN; k++)
            s += h_s[k * BN + b] * w_sm[k * ON + o];
        int oi = (b * TN + t) * ON + o;
        if (oi < out_size) out[oi] = s;
    }
}

extern "C" void kernel_launch(void* const* d_in, const int* in_sizes, int n_in,
                              void* d_out, int out_size)
{
    const int*   x     = (const int*)d_in[0];
    const float* embed = (const float*)d_in[1];
    const float* w_ih  = (const float*)d_in[2];
    const float* b_ih  = (const float*)d_in[3];
    const float* w_hh  = (const float*)d_in[4];
    const float* b_hh  = (const float*)d_in[5];
    const float* w_out = (const float*)d_in[6];
    const float* b_out = (const float*)d_in[7];
    float* out = (float*)d_out;

    cudaFuncSetAttribute(lstm_kernel, cudaFuncAttributeMaxDynamicSharedMemorySize, 98304);
    cudaFuncSetAttribute(proj_kernel, cudaFuncAttributeMaxDynamicSharedMemorySize, 66048);

    zero_flag_kernel<<<(LN * TN * CPL + 255) / 256, 256>>>();
    lstm_kernel<<<NCTA, NTHR, 98304>>>(x, embed, w_ih, b_ih, w_hh, b_hh, out, out_size);
    proj_kernel<<<TN, 256, 66048>>>(w_out, b_out, out, out_size);
}